// round 15
// baseline (speedup 1.0000x reference)
#include <cuda_runtime.h>
#include <cuda_bf16.h>
#include <cstdint>
#include <cmath>

// ----------------------------------------------------------------------------
// Problem dims
// ----------------------------------------------------------------------------
#define NROWS 8192
#define DIM   1024
#define KDIM  2048   // 2*DIM

// GEMM tiling: CTA 128x128, 4 warps (2m x 2n), warp 64x64, K=64/stage, 3 stages
#define M_TILE 128
#define N_TILE 128
#define K_TILE 64
#define NKT    (KDIM / K_TILE)    // 32
#define STAGES 3
#define A_BYTES (M_TILE * K_TILE * 2)     // 16384
#define B_BYTES (N_TILE * K_TILE * 2)     // 16384
#define ST_BYTES (A_BYTES + B_BYTES)      // 32768
#define SMEM_TOTAL (STAGES * ST_BYTES)    // 98304

// producer smem layout (reuses the GEMM stage smem before the pipeline starts)
#define SROW_FLOATS 1032                  // 4 pad + 1024 + 4 pad
#define CB_OFF      (16 * SROW_FLOATS * 4)   // 66048 bytes (16-row staging)
// cb0 at CB_OFF (1024 floats), cb1 at CB_OFF + 4096

// producer assignment (all producers MUST be < 296 = wave-1 residency)
#define ACT_PRODUCERS 256   // idx 0..255, 32 rows each
#define W2_PRODUCERS  32    // idx 256..287, 32 w2 rows each

// ----------------------------------------------------------------------------
// Scratch (device globals: allocation-free rule)
// ----------------------------------------------------------------------------
__device__ __align__(1024) __nv_bfloat16 g_act[(size_t)NROWS * KDIM]; // 32 MB
__device__ __align__(1024) __nv_bfloat16 g_w2 [(size_t)DIM   * KDIM]; // 4 MB
// monotone counters (zero-init at module load); grow by 4 per tile per call.
// Replays: targets already satisfied -> reads may race with same-value rewrites
// (benign: deterministic inputs => bit-identical data).
__device__ int g_act_ctr[NROWS / M_TILE];   // 64
__device__ int g_w2_ctr [DIM / N_TILE];     // 8

// ----------------------------------------------------------------------------
// Helpers
// ----------------------------------------------------------------------------
__device__ __forceinline__ uint32_t smem_u32(const void* p) {
    uint32_t a;
    asm("{ .reg .u64 t; cvta.to.shared.u64 t, %1; cvt.u32.u64 %0, t; }" : "=r"(a) : "l"(p));
    return a;
}

__device__ __forceinline__ void cp_async16(uint32_t dst, const void* src) {
    asm volatile("cp.async.cg.shared.global [%0], [%1], 16;" :: "r"(dst), "l"(src) : "memory");
}
#define CP_COMMIT() asm volatile("cp.async.commit_group;" ::: "memory")
#define CP_WAIT(n)  asm volatile("cp.async.wait_group %0;" :: "n"(n) : "memory")

__device__ __forceinline__ void ldsm_x4(uint32_t* r, uint32_t addr) {
    asm volatile("ldmatrix.sync.aligned.m8n8.x4.shared.b16 {%0,%1,%2,%3}, [%4];"
                 : "=r"(r[0]), "=r"(r[1]), "=r"(r[2]), "=r"(r[3]) : "r"(addr));
}

__device__ __forceinline__ void mma_bf16(float* c, const uint32_t* a, const uint32_t* b) {
    asm volatile(
        "mma.sync.aligned.m16n8k16.row.col.f32.bf16.bf16.f32 "
        "{%0,%1,%2,%3}, {%4,%5,%6,%7}, {%8,%9}, {%0,%1,%2,%3};"
        : "+f"(c[0]), "+f"(c[1]), "+f"(c[2]), "+f"(c[3])
        : "r"(a[0]), "r"(a[1]), "r"(a[2]), "r"(a[3]), "r"(b[0]), "r"(b[1]));
}

__device__ __forceinline__ float gelu_fast(float a) {
    const float u = 0.7978845608028654f * a * (1.0f + 0.044715f * a * a);
    float t;
    asm("tanh.approx.f32 %0, %1;" : "=f"(t) : "f"(u));
    return 0.5f * a * (1.0f + t);
}

// ----------------------------------------------------------------------------
// Mega-kernel: producer prologue (act / w2 conversion) + flags + R12 GEMM core
//   out[m,n] = ifeats[m,n] + b2[n] + sum_k Act[m,k] * W2bf16[n,k]
// ----------------------------------------------------------------------------
__device__ __forceinline__ void issue_half(uint32_t dst, const __nv_bfloat16* g)
{
#pragma unroll
    for (int i = 0; i < 8; i++)
        cp_async16(dst + (uint32_t)(i * 16 * 128), g + (size_t)(i * 16) * KDIM);
}

__global__ void __launch_bounds__(128, 2) gemm_kernel(
    const float* __restrict__ ifeats,
    const float* __restrict__ b2,
    float* __restrict__ out,
    const float* __restrict__ tn,
    const float* __restrict__ ta,
    const float* __restrict__ convw,
    const float* __restrict__ convb,
    const float* __restrict__ w2)
{
    extern __shared__ __align__(1024) char smem[];
    const int tid = threadIdx.x;
    const int bx  = blockIdx.x;          // n-tile 0..7
    const int by  = blockIdx.y;          // m-tile 0..63
    const int idx = by * 8 + bx;         // linear dispatch index

    // ======================= PRODUCER PROLOGUE =======================
    if (idx < ACT_PRODUCERS) {
        // --- produce act rows [idx*32, idx*32+32) ---
        float* srow = (float*)smem;                       // 16 x 1032 floats
        float* scb0 = (float*)(smem + CB_OFF);            // 1024
        float* scb1 = scb0 + DIM;

        // cbase (tn/ta conv const + bias), thread t -> cols t*8..t*8+7
        {
            const float wn0[5] = { convw[0], convw[1], convw[2], convw[3], convw[4] };
            const float wa0[5] = { convw[5], convw[6], convw[7], convw[8], convw[9] };
            const float wn1[5] = { convw[15], convw[16], convw[17], convw[18], convw[19] };
            const float wa1[5] = { convw[20], convw[21], convw[22], convw[23], convw[24] };
            const float b0 = convb[0], b1 = convb[1];
#pragma unroll
            for (int u = 0; u < 8; u++) {
                const int j = tid * 8 + u;
                float c0 = b0, c1 = b1;
#pragma unroll
                for (int w = 0; w < 5; w++) {
                    const int q = j + w - 2;
                    if (q >= 0 && q < DIM) {
                        const float xn = tn[q], xa = ta[q];
                        c0 += wn0[w] * xn + wa0[w] * xa;
                        c1 += wn1[w] * xn + wa1[w] * xa;
                    }
                }
                scb0[j] = c0;
                scb1[j] = c1;
            }
        }

        float wi0[5], wi1[5];
#pragma unroll
        for (int w = 0; w < 5; w++) {
            wi0[w] = convw[10 + w];
            wi1[w] = convw[25 + w];
        }

#pragma unroll 1
        for (int half = 0; half < 2; half++) {
            const int r0 = idx * 32 + half * 16;
            __syncthreads();   // cb ready (h0) / previous half consumed (h1)
            // zero halos: 16 rows x 8 pad words
            if (tid < 128) {
                const int row = tid >> 3, p = tid & 7;
                srow[row * SROW_FLOATS + (p < 4 ? p : 1024 + p)] = 0.f;
            }
            // load 16 rows x 256 float4
#pragma unroll 4
            for (int q = tid; q < 16 * 256; q += 128) {
                const int row = q >> 8, c4 = q & 255;
                ((float4*)(srow + row * SROW_FLOATS + 4))[c4] =
                    ((const float4*)(ifeats + (size_t)(r0 + row) * DIM))[c4];
            }
            __syncthreads();

            // compute: thread -> row (tid>>3), col segment (tid&7)*128
            const int row  = tid >> 3;
            const int cseg = (tid & 7) * 128;
            const float* xp = srow + row * SROW_FLOATS + 2 + cseg; // xp[c..c+4] window
            __nv_bfloat16* out0 = g_act + (size_t)(r0 + row) * KDIM + cseg;
            __nv_bfloat16* out1 = out0 + DIM;

            float x0 = xp[0], x1 = xp[1], x2 = xp[2], x3 = xp[3];
            __align__(8) __nv_bfloat16 o0[4], o1[4];
#pragma unroll 4
            for (int c = 0; c < 128; c++) {
                const float x4 = xp[c + 4];
                float a0 = scb0[cseg + c] + wi0[0]*x0 + wi0[1]*x1 + wi0[2]*x2
                                          + wi0[3]*x3 + wi0[4]*x4;
                float a1 = scb1[cseg + c] + wi1[0]*x0 + wi1[1]*x1 + wi1[2]*x2
                                          + wi1[3]*x3 + wi1[4]*x4;
                o0[c & 3] = __float2bfloat16_rn(gelu_fast(a0));
                o1[c & 3] = __float2bfloat16_rn(gelu_fast(a1));
                if ((c & 3) == 3) {
                    *(uint2*)(out0 + c - 3) = *(uint2*)o0;
                    *(uint2*)(out1 + c - 3) = *(uint2*)o1;
                }
                x0 = x1; x1 = x2; x2 = x3; x3 = x4;
            }
        }
        __threadfence();
        __syncthreads();
        if (tid == 0) atomicAdd(&g_act_ctr[idx >> 2], 1);   // 4 producers per m-tile
    } else if (idx < ACT_PRODUCERS + W2_PRODUCERS) {
        // --- produce w2 bf16 rows [(idx-256)*32, +32) ---
        const int j = idx - ACT_PRODUCERS;
        const size_t base4 = (size_t)j * 16384;             // 32 rows * 2048 / 4
#pragma unroll 4
        for (int q = tid; q < 16384; q += 128) {
            const float4 v = ((const float4*)w2)[base4 + q];
            __align__(8) __nv_bfloat16 o[4] = {
                __float2bfloat16_rn(v.x), __float2bfloat16_rn(v.y),
                __float2bfloat16_rn(v.z), __float2bfloat16_rn(v.w)
            };
            ((uint2*)g_w2)[base4 + q] = *(uint2*)o;
        }
        __threadfence();
        __syncthreads();
        if (tid == 0) atomicAdd(&g_w2_ctr[j >> 2], 1);      // 4 producers per n-tile
    }

    // ======================= FLAG WAIT (acquire) =======================
    if (tid == 0) {
        while (*(volatile int*)&g_act_ctr[by] < 4 ||
               *(volatile int*)&g_w2_ctr[bx]  < 4)
            __nanosleep(64);
        __threadfence();
    }
    __syncthreads();

    // ======================= GEMM CORE (R12 verbatim) =======================
    const uint32_t sb = smem_u32(smem);
    const int lane = tid & 31;
    const int wid  = tid >> 5;
    const int wm   = wid & 1;     // 2 warp rows -> 64 m each
    const int wn   = wid >> 1;    // 2 warp cols -> 64 n each
    const int m0   = by * M_TILE;
    const int n0   = bx * N_TILE;

    const int ldrow = tid >> 3;          // 0..15
    const int ldkc  = tid & 7;
    const uint32_t ldsw = (uint32_t)((ldkc * 16) ^ ((ldrow & 7) << 4));
    const uint32_t dA0 = sb + (uint32_t)(ldrow * 128) + ldsw;
    const uint32_t dB0 = dA0 + A_BYTES;
    const __nv_bfloat16* gA0 = g_act + (size_t)(m0 + ldrow) * KDIM + ldkc * 8;
    const __nv_bfloat16* gB0 = g_w2  + (size_t)(n0 + ldrow) * KDIM + ldkc * 8;

    float acc[4][8][4];
#pragma unroll
    for (int a = 0; a < 4; a++)
#pragma unroll
        for (int b = 0; b < 8; b++)
#pragma unroll
            for (int q = 0; q < 4; q++) acc[a][b][q] = 0.f;

    const uint32_t xsw   = (uint32_t)((lane & 7) << 4);
    const int rowA = wm * 64 + (lane & 7) + ((lane & 8) ? 8 : 0);
    const uint32_t colA0 = (uint32_t)(((lane >> 4) & 1) << 4);
    const int rowB = wn * 64 + (lane & 7) + ((lane & 16) ? 8 : 0);
    const uint32_t colB0 = (uint32_t)(((lane >> 3) & 1) << 4);

    uint32_t af[2][4][4];
    uint32_t bf[2][4][4];

    // prologue: stages 0,1
    issue_half(dA0, gA0); issue_half(dB0, gB0); CP_COMMIT();
    issue_half(dA0 + ST_BYTES, gA0 + K_TILE);
    issue_half(dB0 + ST_BYTES, gB0 + K_TILE); CP_COMMIT();
    CP_WAIT(1);
    __syncthreads();

    // preload kt=0 ks=0 fragments into buf 0
#pragma unroll
    for (int mt = 0; mt < 4; mt++)
        ldsm_x4(af[0][mt], sb + (uint32_t)((rowA + mt * 16) * 128) + (colA0 ^ xsw));
#pragma unroll
    for (int p = 0; p < 4; p++)
        ldsm_x4(bf[0][p], sb + A_BYTES + (uint32_t)((rowB + p * 16) * 128) + (colB0 ^ xsw));

#pragma unroll 1
    for (int kt = 0; kt < NKT; kt++) {
        const uint32_t aBase = sb + (uint32_t)(kt % STAGES) * ST_BYTES;
        const uint32_t bBase = aBase + A_BYTES;
        const uint32_t offN  = (uint32_t)((kt + 2) % STAGES) * ST_BYTES;

#pragma unroll
        for (int ks = 0; ks < 4; ks++) {
            const int cur = ks & 1, nxt = cur ^ 1;

            if (ks < 3) {
                const uint32_t kcol = (uint32_t)((ks + 1) * 32);
#pragma unroll
                for (int mt = 0; mt < 4; mt++)
                    ldsm_x4(af[nxt][mt], aBase + (uint32_t)((rowA + mt * 16) * 128)
                                               + ((kcol + colA0) ^ xsw));
#pragma unroll
                for (int p = 0; p < 4; p++)
                    ldsm_x4(bf[nxt][p], bBase + (uint32_t)((rowB + p * 16) * 128)
                                              + ((kcol + colB0) ^ xsw));
            } else {
                CP_WAIT(1);
                __syncthreads();
                if (kt + 1 < NKT) {
                    const uint32_t aN = sb + (uint32_t)((kt + 1) % STAGES) * ST_BYTES;
                    const uint32_t bN = aN + A_BYTES;
#pragma unroll
                    for (int mt = 0; mt < 4; mt++)
                        ldsm_x4(af[nxt][mt], aN + (uint32_t)((rowA + mt * 16) * 128)
                                                + (colA0 ^ xsw));
#pragma unroll
                    for (int p = 0; p < 4; p++)
                        ldsm_x4(bf[nxt][p], bN + (uint32_t)((rowB + p * 16) * 128)
                                               + (colB0 ^ xsw));
                }
            }

#pragma unroll
            for (int mt = 0; mt < 4; mt++)
#pragma unroll
                for (int nt = 0; nt < 8; nt++)
                    mma_bf16(acc[mt][nt], af[cur][mt], &bf[cur][nt >> 1][(nt & 1) * 2]);

            if (ks == 0) {
                if (kt + 2 < NKT)
                    issue_half(dA0 + offN, gA0 + (size_t)(kt + 2) * K_TILE);
            } else if (ks == 1) {
                if (kt + 2 < NKT)
                    issue_half(dB0 + offN, gB0 + (size_t)(kt + 2) * K_TILE);
                CP_COMMIT();
            }
        }
    }

    // epilogue: out = ifeats + b2 + acc  (b2 hoisted)
    const int cbase = n0 + wn * 64 + ((lane & 3) << 1);
    float2 bv[8];
#pragma unroll
    for (int nt = 0; nt < 8; nt++)
        bv[nt] = *(const float2*)(b2 + cbase + nt * 8);

#pragma unroll
    for (int mt = 0; mt < 4; mt++) {
        const int r0 = m0 + wm * 64 + mt * 16 + (lane >> 2);
        const float* i0p = ifeats + (size_t)r0 * DIM;
        const float* i1p = i0p + (size_t)8 * DIM;
        float* o0p = out + (size_t)r0 * DIM;
        float* o1p = o0p + (size_t)8 * DIM;
#pragma unroll
        for (int nt = 0; nt < 8; nt++) {
            const int c0 = cbase + nt * 8;
            {
                const float2 iv = *(const float2*)(i0p + c0);
                float2 ov;
                ov.x = iv.x + bv[nt].x + acc[mt][nt][0];
                ov.y = iv.y + bv[nt].y + acc[mt][nt][1];
                *(float2*)(o0p + c0) = ov;
            }
            {
                const float2 iv = *(const float2*)(i1p + c0);
                float2 ov;
                ov.x = iv.x + bv[nt].x + acc[mt][nt][2];
                ov.y = iv.y + bv[nt].y + acc[mt][nt][3];
                *(float2*)(o1p + c0) = ov;
            }
        }
    }
}

// ----------------------------------------------------------------------------
// Host launcher — single kernel
// ----------------------------------------------------------------------------
extern "C" void kernel_launch(void* const* d_in, const int* in_sizes, int n_in,
                              void* d_out, int out_size)
{
    const float* ifeats = (const float*)d_in[0];
    const float* tn     = (const float*)d_in[1];
    const float* ta     = (const float*)d_in[2];
    const float* convw  = (const float*)d_in[3];
    const float* convb  = (const float*)d_in[4];
    const float* w2     = (const float*)d_in[5];
    const float* b2     = (const float*)d_in[6];
    float* out = (float*)d_out;

    static bool attr_set = false;
    if (!attr_set) {
        cudaFuncSetAttribute(gemm_kernel, cudaFuncAttributeMaxDynamicSharedMemorySize, SMEM_TOTAL);
        attr_set = true;
    }
    gemm_kernel<<<dim3(DIM / N_TILE, NROWS / M_TILE), 128, SMEM_TOTAL>>>(
        ifeats, b2, out, tn, ta, convw, convb, w2);

    (void)in_sizes; (void)n_in; (void)out_size;
}

// round 16
// speedup vs baseline: 1.2325x; 1.2325x over previous
#include <cuda_runtime.h>
#include <cuda_bf16.h>
#include <cstdint>
#include <cmath>

// ----------------------------------------------------------------------------
// Problem dims
// ----------------------------------------------------------------------------
#define NROWS 8192
#define DIM   1024
#define KDIM  2048   // 2*DIM

// GEMM tiling: CTA 128x128, 4 warps (2m x 2n), warp 64x64, K=64/stage, 3 stages
#define M_TILE 128
#define N_TILE 128
#define K_TILE 64
#define NKT    (KDIM / K_TILE)    // 32
#define STAGES 3
#define A_BYTES (M_TILE * K_TILE * 2)     // 16384
#define B_BYTES (N_TILE * K_TILE * 2)     // 16384
#define ST_BYTES (A_BYTES + B_BYTES)      // 32768
#define SMEM_TOTAL (STAGES * ST_BYTES)    // 98304

// fused act launch: [conv 4 rows/block][w2cvt 8 elems/thread]
#define CONV_BLOCKS  (NROWS / 4)                // 2048
#define W2CVT_BLOCKS ((DIM * KDIM / 8) / 256)   // 1024
#define ACT_GRID     (CONV_BLOCKS + W2CVT_BLOCKS)

// ----------------------------------------------------------------------------
// Scratch (device globals: allocation-free rule)
// ----------------------------------------------------------------------------
__device__ __align__(1024) __nv_bfloat16 g_act[(size_t)NROWS * KDIM]; // 32 MB
__device__ __align__(1024) __nv_bfloat16 g_w2 [(size_t)DIM   * KDIM]; // 4 MB

// ----------------------------------------------------------------------------
// Helpers
// ----------------------------------------------------------------------------
__device__ __forceinline__ uint32_t smem_u32(const void* p) {
    uint32_t a;
    asm("{ .reg .u64 t; cvta.to.shared.u64 t, %1; cvt.u32.u64 %0, t; }" : "=r"(a) : "l"(p));
    return a;
}

__device__ __forceinline__ void cp_async16(uint32_t dst, const void* src) {
    asm volatile("cp.async.cg.shared.global [%0], [%1], 16;" :: "r"(dst), "l"(src) : "memory");
}
#define CP_COMMIT() asm volatile("cp.async.commit_group;" ::: "memory")
#define CP_WAIT(n)  asm volatile("cp.async.wait_group %0;" :: "n"(n) : "memory")

__device__ __forceinline__ void ldsm_x4(uint32_t* r, uint32_t addr) {
    asm volatile("ldmatrix.sync.aligned.m8n8.x4.shared.b16 {%0,%1,%2,%3}, [%4];"
                 : "=r"(r[0]), "=r"(r[1]), "=r"(r[2]), "=r"(r[3]) : "r"(addr));
}

__device__ __forceinline__ void mma_bf16(float* c, const uint32_t* a, const uint32_t* b) {
    asm volatile(
        "mma.sync.aligned.m16n8k16.row.col.f32.bf16.bf16.f32 "
        "{%0,%1,%2,%3}, {%4,%5,%6,%7}, {%8,%9}, {%0,%1,%2,%3};"
        : "+f"(c[0]), "+f"(c[1]), "+f"(c[2]), "+f"(c[3])
        : "r"(a[0]), "r"(a[1]), "r"(a[2]), "r"(a[3]), "r"(b[0]), "r"(b[1]));
}

__device__ __forceinline__ float gelu_fast(float a) {
    const float u = 0.7978845608028654f * a * (1.0f + 0.044715f * a * a);
    float t;
    asm("tanh.approx.f32 %0, %1;" : "=f"(t) : "f"(u));
    return 0.5f * a * (1.0f + t);
}

// ----------------------------------------------------------------------------
// Kernel 1 (fused, no cross-CTA deps):
//   blocks [0, CONV_BLOCKS):  4 sample rows: inline cbase + conv + GELU -> bf16
//   blocks [CONV_BLOCKS, +W2CVT_BLOCKS): w2 fp32 -> bf16
// ----------------------------------------------------------------------------
__global__ void __launch_bounds__(256) act_kernel(
    const float* __restrict__ ifeats, const float* __restrict__ convw,
    const float* __restrict__ w2,     const float* __restrict__ tn,
    const float* __restrict__ ta,     const float* __restrict__ convb)
{
    const int t = threadIdx.x;

    if (blockIdx.x >= CONV_BLOCKS) {
        // ---- w2 convert: 8 elems per thread ----
        const int idx = ((blockIdx.x - CONV_BLOCKS) * 256 + t) * 2;
#pragma unroll
        for (int u = 0; u < 2; u++) {
            const float4 v = ((const float4*)w2)[idx + u];
            __align__(8) __nv_bfloat16 o[4] = {
                __float2bfloat16_rn(v.x), __float2bfloat16_rn(v.y),
                __float2bfloat16_rn(v.z), __float2bfloat16_rn(v.w)
            };
            ((uint2*)g_w2)[idx + u] = *(uint2*)o;
        }
        return;
    }

    // ---- conv + inline cbase + GELU for 4 rows ----
    __shared__ __align__(16) float s_in[4][DIM + 8];
    __shared__ __align__(16) float s_tn[DIM + 8];
    __shared__ __align__(16) float s_ta[DIM + 8];
    const int i0 = blockIdx.x * 4;

    if (t < 4) {
#pragma unroll
        for (int r = 0; r < 4; r++) { s_in[r][t] = 0.f; s_in[r][DIM + 4 + t] = 0.f; }
        s_tn[t] = 0.f; s_tn[DIM + 4 + t] = 0.f;
        s_ta[t] = 0.f; s_ta[DIM + 4 + t] = 0.f;
    }
#pragma unroll
    for (int r = 0; r < 4; r++)
        ((float4*)(s_in[r] + 4))[t] = ((const float4*)(ifeats + (size_t)(i0 + r) * DIM))[t];
    ((float4*)(s_tn + 4))[t] = ((const float4*)tn)[t];
    ((float4*)(s_ta + 4))[t] = ((const float4*)ta)[t];

    float wn0[5], wa0[5], wi0[5], wn1[5], wa1[5], wi1[5];
#pragma unroll
    for (int w = 0; w < 5; w++) {
        wn0[w] = __ldg(convw + w);      wa0[w] = __ldg(convw + 5 + w);
        wi0[w] = __ldg(convw + 10 + w);
        wn1[w] = __ldg(convw + 15 + w); wa1[w] = __ldg(convw + 20 + w);
        wi1[w] = __ldg(convw + 25 + w);
    }
    const float b0 = convb[0], b1 = convb[1];
    __syncthreads();

    // inline cbase for this thread's 4 columns (zero-halo FMAs == exact skip)
    const int j0 = t * 4;
    float c0a[4], c1a[4];
#pragma unroll
    for (int jj = 0; jj < 4; jj++) {
        float c0 = b0, c1 = b1;
#pragma unroll
        for (int w = 0; w < 5; w++) {
            const float xn = s_tn[j0 + jj + w + 2];
            const float xa = s_ta[j0 + jj + w + 2];
            c0 += wn0[w] * xn + wa0[w] * xa;
            c1 += wn1[w] * xn + wa1[w] * xa;
        }
        c0a[jj] = c0;
        c1a[jj] = c1;
    }

#pragma unroll
    for (int r = 0; r < 4; r++) {
        float x[8];
#pragma unroll
        for (int q = 0; q < 8; q++) x[q] = s_in[r][j0 + 2 + q];

        __nv_bfloat16* outr = g_act + (size_t)(i0 + r) * KDIM;
        __align__(8) __nv_bfloat16 o0[4], o1[4];
#pragma unroll
        for (int jj = 0; jj < 4; jj++) {
            float a0 = c0a[jj], a1 = c1a[jj];
#pragma unroll
            for (int w = 0; w < 5; w++) {
                const float xi = x[jj + w];
                a0 += wi0[w] * xi;
                a1 += wi1[w] * xi;
            }
            o0[jj] = __float2bfloat16_rn(gelu_fast(a0));
            o1[jj] = __float2bfloat16_rn(gelu_fast(a1));
        }
        *(uint2*)(outr + j0)       = *(uint2*)o0;
        *(uint2*)(outr + DIM + j0) = *(uint2*)o1;
    }
}

// ----------------------------------------------------------------------------
// Kernel 3: mma.sync bf16 GEMM (R12 verbatim: 3-stage, cross-kt frag pipeline,
// split A/B copy issue). CTA 128x128, 128 threads, 4 warps (2x2), warp 64x64,
// 2 CTA/SM.
//   out[m,n] = ifeats[m,n] + b2[n] + sum_k g_act[m,k] * g_w2[n,k]
// ----------------------------------------------------------------------------
__device__ __forceinline__ void issue_half(uint32_t dst, const __nv_bfloat16* g)
{
#pragma unroll
    for (int i = 0; i < 8; i++)
        cp_async16(dst + (uint32_t)(i * 16 * 128), g + (size_t)(i * 16) * KDIM);
}

__global__ void __launch_bounds__(128, 2) gemm_kernel(
    const float* __restrict__ ifeats,
    const float* __restrict__ b2,
    float* __restrict__ out)
{
    extern __shared__ __align__(1024) char smem[];
    const uint32_t sb = smem_u32(smem);
    const int tid  = threadIdx.x;
    const int lane = tid & 31;
    const int wid  = tid >> 5;
    const int wm   = wid & 1;     // 2 warp rows -> 64 m each
    const int wn   = wid >> 1;    // 2 warp cols -> 64 n each
    const int m0   = blockIdx.y * M_TILE;
    const int n0   = blockIdx.x * N_TILE;

    // per-thread cp.async bases
    const int ldrow = tid >> 3;          // 0..15
    const int ldkc  = tid & 7;
    const uint32_t ldsw = (uint32_t)((ldkc * 16) ^ ((ldrow & 7) << 4));
    const uint32_t dA0 = sb + (uint32_t)(ldrow * 128) + ldsw;
    const uint32_t dB0 = dA0 + A_BYTES;
    const __nv_bfloat16* gA0 = g_act + (size_t)(m0 + ldrow) * KDIM + ldkc * 8;
    const __nv_bfloat16* gB0 = g_w2  + (size_t)(n0 + ldrow) * KDIM + ldkc * 8;

    float acc[4][8][4];
#pragma unroll
    for (int a = 0; a < 4; a++)
#pragma unroll
        for (int b = 0; b < 8; b++)
#pragma unroll
            for (int q = 0; q < 4; q++) acc[a][b][q] = 0.f;

    const uint32_t xsw   = (uint32_t)((lane & 7) << 4);
    const int rowA = wm * 64 + (lane & 7) + ((lane & 8) ? 8 : 0);
    const uint32_t colA0 = (uint32_t)(((lane >> 4) & 1) << 4);
    const int rowB = wn * 64 + (lane & 7) + ((lane & 16) ? 8 : 0);
    const uint32_t colB0 = (uint32_t)(((lane >> 3) & 1) << 4);

    uint32_t af[2][4][4];
    uint32_t bf[2][4][4];

    // prologue: stages 0,1
    issue_half(dA0, gA0); issue_half(dB0, gB0); CP_COMMIT();
    issue_half(dA0 + ST_BYTES, gA0 + K_TILE);
    issue_half(dB0 + ST_BYTES, gB0 + K_TILE); CP_COMMIT();
    CP_WAIT(1);
    __syncthreads();

    // preload kt=0 ks=0 fragments into buf 0
#pragma unroll
    for (int mt = 0; mt < 4; mt++)
        ldsm_x4(af[0][mt], sb + (uint32_t)((rowA + mt * 16) * 128) + (colA0 ^ xsw));
#pragma unroll
    for (int p = 0; p < 4; p++)
        ldsm_x4(bf[0][p], sb + A_BYTES + (uint32_t)((rowB + p * 16) * 128) + (colB0 ^ xsw));

#pragma unroll 1
    for (int kt = 0; kt < NKT; kt++) {
        const uint32_t aBase = sb + (uint32_t)(kt % STAGES) * ST_BYTES;
        const uint32_t bBase = aBase + A_BYTES;
        const uint32_t offN  = (uint32_t)((kt + 2) % STAGES) * ST_BYTES;

#pragma unroll
        for (int ks = 0; ks < 4; ks++) {
            const int cur = ks & 1, nxt = cur ^ 1;

            // 1) fragment prefetch for next k-step (or next stage at ks3)
            if (ks < 3) {
                const uint32_t kcol = (uint32_t)((ks + 1) * 32);
#pragma unroll
                for (int mt = 0; mt < 4; mt++)
                    ldsm_x4(af[nxt][mt], aBase + (uint32_t)((rowA + mt * 16) * 128)
                                               + ((kcol + colA0) ^ xsw));
#pragma unroll
                for (int p = 0; p < 4; p++)
                    ldsm_x4(bf[nxt][p], bBase + (uint32_t)((rowB + p * 16) * 128)
                                              + ((kcol + colB0) ^ xsw));
            } else {
                CP_WAIT(1);
                __syncthreads();
                if (kt + 1 < NKT) {
                    const uint32_t aN = sb + (uint32_t)((kt + 1) % STAGES) * ST_BYTES;
                    const uint32_t bN = aN + A_BYTES;
#pragma unroll
                    for (int mt = 0; mt < 4; mt++)
                        ldsm_x4(af[nxt][mt], aN + (uint32_t)((rowA + mt * 16) * 128)
                                                + (colA0 ^ xsw));
#pragma unroll
                    for (int p = 0; p < 4; p++)
                        ldsm_x4(bf[nxt][p], bN + (uint32_t)((rowB + p * 16) * 128)
                                               + (colB0 ^ xsw));
                }
            }

            // 2) MMAs for current k-step
#pragma unroll
            for (int mt = 0; mt < 4; mt++)
#pragma unroll
                for (int nt = 0; nt < 8; nt++)
                    mma_bf16(acc[mt][nt], af[cur][mt], &bf[cur][nt >> 1][(nt & 1) * 2]);

            // 3) copy issue behind the MMA shadow: A at ks0, B at ks1
            if (ks == 0) {
                if (kt + 2 < NKT)
                    issue_half(dA0 + offN, gA0 + (size_t)(kt + 2) * K_TILE);
            } else if (ks == 1) {
                if (kt + 2 < NKT)
                    issue_half(dB0 + offN, gB0 + (size_t)(kt + 2) * K_TILE);
                CP_COMMIT();
            }
        }
    }

    // epilogue: out = ifeats + b2 + acc  (b2 hoisted out of mt loop)
    const int cbase = n0 + wn * 64 + ((lane & 3) << 1);
    float2 bv[8];
#pragma unroll
    for (int nt = 0; nt < 8; nt++)
        bv[nt] = *(const float2*)(b2 + cbase + nt * 8);

#pragma unroll
    for (int mt = 0; mt < 4; mt++) {
        const int r0 = m0 + wm * 64 + mt * 16 + (lane >> 2);
        const float* i0p = ifeats + (size_t)r0 * DIM;
        const float* i1p = i0p + (size_t)8 * DIM;
        float* o0p = out + (size_t)r0 * DIM;
        float* o1p = o0p + (size_t)8 * DIM;
#pragma unroll
        for (int nt = 0; nt < 8; nt++) {
            const int c0 = cbase + nt * 8;
            {
                const float2 iv = *(const float2*)(i0p + c0);
                float2 ov;
                ov.x = iv.x + bv[nt].x + acc[mt][nt][0];
                ov.y = iv.y + bv[nt].y + acc[mt][nt][1];
                *(float2*)(o0p + c0) = ov;
            }
            {
                const float2 iv = *(const float2*)(i1p + c0);
                float2 ov;
                ov.x = iv.x + bv[nt].x + acc[mt][nt][2];
                ov.y = iv.y + bv[nt].y + acc[mt][nt][3];
                *(float2*)(o1p + c0) = ov;
            }
        }
    }
}

// ----------------------------------------------------------------------------
// Host launcher
// ----------------------------------------------------------------------------
extern "C" void kernel_launch(void* const* d_in, const int* in_sizes, int n_in,
                              void* d_out, int out_size)
{
    const float* ifeats = (const float*)d_in[0];
    const float* tn     = (const float*)d_in[1];
    const float* ta     = (const float*)d_in[2];
    const float* convw  = (const float*)d_in[3];
    const float* convb  = (const float*)d_in[4];
    const float* w2     = (const float*)d_in[5];
    const float* b2     = (const float*)d_in[6];
    float* out = (float*)d_out;

    act_kernel<<<ACT_GRID, 256>>>(ifeats, convw, w2, tn, ta, convb);

    static bool attr_set = false;
    if (!attr_set) {
        cudaFuncSetAttribute(gemm_kernel, cudaFuncAttributeMaxDynamicSharedMemorySize, SMEM_TOTAL);
        attr_set = true;
    }
    gemm_kernel<<<dim3(DIM / N_TILE, NROWS / M_TILE), 128, SMEM_TOTAL>>>(ifeats, b2, out);

    (void)in_sizes; (void)n_in; (void)out_size;
}